// round 1
// baseline (speedup 1.0000x reference)
#include <cuda_runtime.h>
#include <cstdint>

// PatchEmbed permute: x[16,64,256,256] f32 -> out[16, 64*64, 64*4*4]
// out[n, wp, hp, c, pi, pj] = x[n, c, hp*4+pi, wp*4+pj]
// pj (4 floats, contiguous both sides) => treat as float4 elements.
// Per (n, hp): transpose M[cp=256][wp=64] of float4 where cp = c*4+pi.
//   input  f4 idx = ((n*64 + c)*256 + hp*4 + pi)*64 + wp   (contiguous in wp)
//   output f4 idx = ((n*64 + wp)*64 + hp)*256 + cp          (contiguous in cp)

#define N_ 16
#define C_ 64
#define HP_ 64
#define WP_ 64
#define CP_ 256           // C_*4
#define CP_TILE 32
#define THREADS 256

__global__ __launch_bounds__(THREADS)
void patch_permute_kernel(const float4* __restrict__ in, float4* __restrict__ out) {
    __shared__ float4 tile[CP_TILE][WP_ + 1];   // +1 f4 pad: conflict-free transposed reads

    const int cpt = blockIdx.x;    // 0..7   (cp tile)
    const int hp  = blockIdx.y;    // 0..63
    const int n   = blockIdx.z;    // 0..15
    const int tid = threadIdx.x;

    // ---- load: coalesced over wp (32 consecutive float4 = 512B per warp) ----
#pragma unroll
    for (int i = 0; i < (CP_TILE * WP_) / THREADS; i++) {
        int idx = i * THREADS + tid;
        int cpl = idx >> 6;          // 0..31
        int wp  = idx & 63;          // 0..63
        int cp  = cpt * CP_TILE + cpl;
        int c   = cp >> 2;
        int pi  = cp & 3;
        int in_idx = ((n * C_ + c) * 256 + hp * 4 + pi) * WP_ + wp;
        tile[cpl][wp] = in[in_idx];
    }
    __syncthreads();

    // ---- store: coalesced over cp (32 consecutive float4 = 512B per warp) ----
#pragma unroll
    for (int i = 0; i < (CP_TILE * WP_) / THREADS; i++) {
        int idx = i * THREADS + tid;
        int wp  = idx >> 5;          // 0..63
        int cpl = idx & 31;          // 0..31
        int cp  = cpt * CP_TILE + cpl;
        int out_idx = ((n * WP_ + wp) * HP_ + hp) * CP_ + cp;
        out[out_idx] = tile[cpl][wp];
    }
}

// ori_shape = (16, 64, 256, 256), written numerically past the data region.
__global__ void tail_kernel(float* __restrict__ out, int start, int count) {
    const float vals[4] = {16.0f, 64.0f, 256.0f, 256.0f};
    int t = threadIdx.x;
    if (t < count && t < 4) out[start + t] = vals[t];
}

extern "C" void kernel_launch(void* const* d_in, const int* in_sizes, int n_in,
                              void* d_out, int out_size) {
    (void)in_sizes; (void)n_in;
    const float4* in  = (const float4*)d_in[0];
    float4*       out = (float4*)d_out;

    dim3 grid(CP_ / CP_TILE, HP_, N_);   // 8 x 64 x 16 = 8192 blocks
    patch_permute_kernel<<<grid, THREADS>>>(in, out);

    const int NDATA = N_ * C_ * 256 * 256;   // 67,108,864 data elements
    if (out_size > NDATA) {
        int cnt = out_size - NDATA;
        tail_kernel<<<1, 32>>>((float*)d_out, NDATA, cnt);
    }
}

// round 2
// speedup vs baseline: 1.0172x; 1.0172x over previous
#include <cuda_runtime.h>
#include <cstdint>

// PatchEmbed permute: x[16,64,256,256] f32 -> out[16, 64*64, 64*4*4]
// out[n, wp, hp, c, pi, pj] = x[n, c, hp*4+pi, wp*4+pj]
// pj (4 floats, contiguous both sides) => treat as float4 elements.
// Per (n, hp): transpose M[cp=256][wp=64] of float4 where cp = c*4+pi.
//   input  f4 idx = ((n*64 + c)*256 + hp*4 + pi)*64 + wp   (contiguous in wp)
//   output f4 idx = ((n*64 + wp)*64 + hp)*256 + cp          (contiguous in cp)
// Tail: ori_shape = (16,64,256,256) written numerically past the data region,
// fused into the main kernel (a separate launch cost 3.58us of pure overhead).

#define N_ 16
#define C_ 64
#define HP_ 64
#define WP_ 64
#define CP_ 256           // C_*4
#define CP_TILE 32
#define THREADS 256
#define NDATA_F4 (N_ * C_ * 256 * 64)      // data size in float4 units
#define NDATA    (N_ * C_ * 256 * 256)     // data size in floats

__global__ __launch_bounds__(THREADS)
void patch_permute_kernel(const float4* __restrict__ in, float4* __restrict__ out,
                          int tail_count) {
    __shared__ float4 tile[CP_TILE][WP_ + 1];   // +1 f4 pad: conflict-free transposed reads

    const int cpt = blockIdx.x;    // 0..7   (cp tile)
    const int hp  = blockIdx.y;    // 0..63
    const int n   = blockIdx.z;    // 0..15
    const int tid = threadIdx.x;

    // ---- fused tail write (ori_shape), done by one block only ----
    if (cpt == 0 && hp == 0 && n == 0 && tid < 4 && tid < tail_count) {
        const float vals[4] = {16.0f, 64.0f, 256.0f, 256.0f};
        ((float*)out)[NDATA + tid] = vals[tid];
    }

    // ---- load: coalesced over wp (32 consecutive float4 = 512B per warp) ----
#pragma unroll
    for (int i = 0; i < (CP_TILE * WP_) / THREADS; i++) {
        int idx = i * THREADS + tid;
        int cpl = idx >> 6;          // 0..31
        int wp  = idx & 63;          // 0..63
        int cp  = cpt * CP_TILE + cpl;
        int c   = cp >> 2;
        int pi  = cp & 3;
        int in_idx = ((n * C_ + c) * 256 + hp * 4 + pi) * WP_ + wp;
        tile[cpl][wp] = in[in_idx];
    }
    __syncthreads();

    // ---- store: coalesced over cp (32 consecutive float4 = 512B per warp) ----
#pragma unroll
    for (int i = 0; i < (CP_TILE * WP_) / THREADS; i++) {
        int idx = i * THREADS + tid;
        int wp  = idx >> 5;          // 0..63
        int cpl = idx & 31;          // 0..31
        int cp  = cpt * CP_TILE + cpl;
        int out_idx = ((n * WP_ + wp) * HP_ + hp) * CP_ + cp;
        out[out_idx] = tile[cpl][wp];
    }
}

extern "C" void kernel_launch(void* const* d_in, const int* in_sizes, int n_in,
                              void* d_out, int out_size) {
    (void)in_sizes; (void)n_in;
    const float4* in  = (const float4*)d_in[0];
    float4*       out = (float4*)d_out;

    int tail_count = out_size > NDATA ? (out_size - NDATA) : 0;

    dim3 grid(CP_ / CP_TILE, HP_, N_);   // 8 x 64 x 16 = 8192 blocks
    patch_permute_kernel<<<grid, THREADS>>>(in, out, tail_count);
}

// round 3
// speedup vs baseline: 1.1424x; 1.1231x over previous
#include <cuda_runtime.h>
#include <cstdint>

// PatchEmbed permute: x[16,64,256,256] f32 -> out[16, 64*64, 64*4*4]
// out[n, wp, hp, c, pi, pj] = x[n, c, hp*4+pi, wp*4+pj]
// pj (4 floats) => float4 elements. Per (n, hp): transpose M[cp=256][wp=64]
// of float4 where cp = c*4+pi.
//   input  f4 idx = ((n*64 + c)*256 + hp*4 + pi)*64 + wp   (contiguous in wp)
//   output f4 idx = ((n*64 + wp)*64 + hp)*256 + cp          (contiguous in cp)
//
// R3: XOR-swizzled smem tile (32KB exactly, no pad) + 512-thread blocks at
// __launch_bounds__(512,4) -> 64 warps/SM (full occupancy) for more MLP.
// Swizzle col = wp ^ (cpl & 7): bank = (col*4) mod 32; within every 8-lane
// LDS.128 phase, col mod 8 is distinct on BOTH the row-major smem store
// (consecutive wp, fixed cpl) and the transposed smem read (consecutive cpl,
// fixed wp) -> conflict-free.

#define N_ 16
#define C_ 64
#define HP_ 64
#define WP_ 64
#define CP_ 256           // C_*4
#define CP_TILE 32
#define THREADS 512
#define NDATA    (N_ * C_ * 256 * 256)     // data size in floats

__global__ __launch_bounds__(THREADS, 4)
void patch_permute_kernel(const float4* __restrict__ in, float4* __restrict__ out,
                          int tail_count) {
    __shared__ float4 tile[CP_TILE][WP_];   // 32 KB, XOR-swizzled

    const int cpt = blockIdx.x;    // 0..7   (cp tile)
    const int hp  = blockIdx.y;    // 0..63
    const int n   = blockIdx.z;    // 0..15
    const int tid = threadIdx.x;

    // ---- fused tail write (ori_shape = 16,64,256,256), one block only ----
    if (cpt == 0 && hp == 0 && n == 0 && tid < 4 && tid < tail_count) {
        const float vals[4] = {16.0f, 64.0f, 256.0f, 256.0f};
        ((float*)out)[NDATA + tid] = vals[tid];
    }

    // ---- load: coalesced over wp (512B per warp), swizzled smem store ----
#pragma unroll
    for (int i = 0; i < (CP_TILE * WP_) / THREADS; i++) {   // 4 iters
        int idx = i * THREADS + tid;
        int cpl = idx >> 6;          // 0..31
        int wp  = idx & 63;          // 0..63
        int cp  = cpt * CP_TILE + cpl;
        int c   = cp >> 2;
        int pi  = cp & 3;
        int in_idx = ((n * C_ + c) * 256 + hp * 4 + pi) * WP_ + wp;
        tile[cpl][wp ^ (cpl & 7)] = in[in_idx];
    }
    __syncthreads();

    // ---- store: coalesced over cp (512B per warp), swizzled smem read ----
#pragma unroll
    for (int i = 0; i < (CP_TILE * WP_) / THREADS; i++) {   // 4 iters
        int idx = i * THREADS + tid;
        int wp  = idx >> 5;          // 0..63
        int cpl = idx & 31;          // 0..31
        int cp  = cpt * CP_TILE + cpl;
        int out_idx = ((n * WP_ + wp) * HP_ + hp) * CP_ + cp;
        out[out_idx] = tile[cpl][wp ^ (cpl & 7)];
    }
}

extern "C" void kernel_launch(void* const* d_in, const int* in_sizes, int n_in,
                              void* d_out, int out_size) {
    (void)in_sizes; (void)n_in;
    const float4* in  = (const float4*)d_in[0];
    float4*       out = (float4*)d_out;

    int tail_count = out_size > NDATA ? (out_size - NDATA) : 0;

    dim3 grid(CP_ / CP_TILE, HP_, N_);   // 8 x 64 x 16 = 8192 blocks
    patch_permute_kernel<<<grid, THREADS>>>(in, out, tail_count);
}